// round 4
// baseline (speedup 1.0000x reference)
#include <cuda_runtime.h>
#include <cstdint>

#define N_DIM   256
#define BS      256
#define TMAX    1000
#define STEP_F  0.01f
#define EPS_F   0.001f

#define CPC     2                 // batch columns per CTA
#define GRID    (BS / CPC)        // 128 CTAs
#define THREADS 512               // 16 warps -> 4 warps/SMSP

// Warp w (0..15) owns rows [w*16, w*16+16).
// Lane l: rg = l>>3 (0..3), kl = l&7 -> K-slice [kl*32, kl*32+32).
// Thread rows: w*16 + rg*4 + i, i in [0,4). i<2 -> A in registers, i>=2 -> A in smem.
// After the 8-lane butterfly (over both columns at once), lane l owns
// (row = w*16 + rg*4 + (kl>>1), col = kl&1).

#define SA_F4      8192           // 128 KB of A in smem
#define SX_FLOATS  (2 * 2 * 256)  // double-buffered x, 2 columns, permuted layout
#define SMEM_BYTES (SA_F4 * 16 + SX_FLOATS * 4)

union F4 { float4 v; float2 h[2]; };

__device__ __forceinline__ void fma2(float2& d, const float2& a, const float2& b) {
    asm("fma.rn.f32x2 %0, %1, %2, %0;"
        : "+l"(reinterpret_cast<unsigned long long&>(d))
        : "l"(reinterpret_cast<const unsigned long long&>(a)),
          "l"(reinterpret_cast<const unsigned long long&>(b)));
}

__device__ __forceinline__ int permx(int k) {
    // k = (kl<<5) | (j<<2) | e  ->  (j<<5) | (kl<<2) | e
    return (((k >> 2) & 7) << 5) | ((k >> 5) << 2) | (k & 3);
}

__device__ __forceinline__ float a_elem(const float* __restrict__ W, int r, int k) {
    if (k > r) return  __ldg(&W[r * N_DIM + k]);
    if (k < r) return -__ldg(&W[k * N_DIM + r]);
    return -EPS_F;
}

// Accurate fast tanh: tanh(|y|) = 1 - 2/(exp(2|y|)+1), via ex2.approx + rcp.approx.
__device__ __forceinline__ float fast_tanh(float y) {
    float ay = fabsf(y);
    float e;
    asm("ex2.approx.f32 %0, %1;" : "=f"(e) : "f"(ay * 2.8853900817779268f)); // 2*log2(e)
    float r;
    asm("rcp.approx.f32 %0, %1;" : "=f"(r) : "f"(e + 1.0f));
    float t = fmaf(-2.0f, r, 1.0f);
    return copysignf(t, y);
}

// Butterfly reduce-scatter over 8-lane group: v[8] -> lane kl owns sum of v[kl].
__device__ __forceinline__ float reduce8(float* v, int kl) {
    {   bool hi = (kl & 4) != 0;
        #pragma unroll
        for (int i = 0; i < 4; i++) {
            float send = hi ? v[i] : v[i + 4];
            float recv = __shfl_xor_sync(0xffffffffu, send, 4);
            v[i] = (hi ? v[i + 4] : v[i]) + recv;
        }
    }
    {   bool hi = (kl & 2) != 0;
        #pragma unroll
        for (int i = 0; i < 2; i++) {
            float send = hi ? v[i] : v[i + 2];
            float recv = __shfl_xor_sync(0xffffffffu, send, 2);
            v[i] = (hi ? v[i + 2] : v[i]) + recv;
        }
    }
    {   bool hi = (kl & 1) != 0;
        float send = hi ? v[0] : v[1];
        float recv = __shfl_xor_sync(0xffffffffu, send, 1);
        return (hi ? v[1] : v[0]) + recv;
    }
}

extern "C" __global__ void __launch_bounds__(THREADS, 1)
antisym_rnn_kernel(const float* __restrict__ X0,
                   const float* __restrict__ W,
                   const float* __restrict__ by,
                   float* __restrict__ out)
{
    extern __shared__ float smem[];
    float4* sA = reinterpret_cast<float4*>(smem);           // [8192] f4
    float*  sX = smem + SA_F4 * 4;                          // [2][2][256] permuted

    const int tid = threadIdx.x;
    const int w   = tid >> 5;          // warp 0..15
    const int l   = tid & 31;          // lane
    const int rg  = l >> 3;            // row-group 0..3
    const int kl  = l & 7;             // K-lane 0..7
    const int col0 = blockIdx.x * CPC;
    const int row_base = w * 16 + rg * 4;     // this thread's 4 rows start here
    const int k_base   = kl * 32;             // this thread's K slice
    const int my_row   = row_base + (kl >> 1);  // owned after reduction
    const int my_col   = kl & 1;

    // ---- one-time init ----
    float4 areg[2][8];
    #pragma unroll
    for (int i = 0; i < 2; i++) {
        int r = row_base + i;
        #pragma unroll
        for (int j = 0; j < 8; j++) {
            int k = k_base + j * 4;
            areg[i][j] = make_float4(a_elem(W, r, k),     a_elem(W, r, k + 1),
                                     a_elem(W, r, k + 2), a_elem(W, r, k + 3));
        }
    }
    #pragma unroll
    for (int i2 = 0; i2 < 2; i2++) {
        int r = row_base + 2 + i2;
        #pragma unroll
        for (int j = 0; j < 8; j++) {
            int k = k_base + j * 4;
            sA[((i2 * 8 + j) * 16 + w) * 32 + l] =
                make_float4(a_elem(W, r, k),     a_elem(W, r, k + 1),
                            a_elem(W, r, k + 2), a_elem(W, r, k + 3));
        }
    }
    const float byv = by[my_row];

    // x0: permuted smem copy + t=0 output (512 threads cover 2 cols x 256 rows)
    {
        int c  = tid >> 8;
        int rr = tid & 255;
        float v = X0[(col0 + c) * N_DIM + rr];
        sX[(0 * 2 + c) * 256 + permx(rr)] = v;
        out[(size_t)(col0 + c) * (TMAX * N_DIM) + rr] = v;
    }
    float xr = X0[(col0 + my_col) * N_DIM + my_row];   // this lane's own (row,col) value
    __syncthreads();

    int buf = 0;
    for (int t = 1; t < TMAX; ++t) {
        const float4* x0p = reinterpret_cast<const float4*>(sX + (buf * 2 + 0) * 256);
        const float4* x1p = reinterpret_cast<const float4*>(sX + (buf * 2 + 1) * 256);

        float2 acc[4][2];
        #pragma unroll
        for (int i = 0; i < 4; i++) { acc[i][0] = make_float2(0.f, 0.f);
                                      acc[i][1] = make_float2(0.f, 0.f); }

        #pragma unroll
        for (int j = 0; j < 8; j++) {
            F4 xa; xa.v = x0p[j * 8 + kl];
            F4 xb; xb.v = x1p[j * 8 + kl];
            #pragma unroll
            for (int i = 0; i < 2; i++) {
                F4 a; a.v = areg[i][j];
                fma2(acc[i][0], a.h[0], xa.h[0]); fma2(acc[i][0], a.h[1], xa.h[1]);
                fma2(acc[i][1], a.h[0], xb.h[0]); fma2(acc[i][1], a.h[1], xb.h[1]);
            }
            #pragma unroll
            for (int i2 = 0; i2 < 2; i2++) {
                F4 a; a.v = sA[((i2 * 8 + j) * 16 + w) * 32 + l];
                fma2(acc[2 + i2][0], a.h[0], xa.h[0]); fma2(acc[2 + i2][0], a.h[1], xa.h[1]);
                fma2(acc[2 + i2][1], a.h[0], xb.h[0]); fma2(acc[2 + i2][1], a.h[1], xb.h[1]);
            }
        }

        // v[m], m = i*2 + c  (i row-offset 0..3, c col 0..1)
        float v[8];
        #pragma unroll
        for (int i = 0; i < 4; i++) {
            v[i * 2 + 0] = acc[i][0].x + acc[i][0].y;
            v[i * 2 + 1] = acc[i][1].x + acc[i][1].y;
        }

        // single butterfly handles both columns; lane kl owns (row rg*4+(kl>>1), col kl&1)
        float y = reduce8(v, kl) + byv;

        float xn = xr + STEP_F * fast_tanh(y);
        xr = xn;

        const int nbuf = buf ^ 1;
        sX[(nbuf * 2 + my_col) * 256 + permx(my_row)] = xn;
        out[(size_t)(col0 + my_col) * (TMAX * N_DIM) + (size_t)t * N_DIM + my_row] = xn;

        __syncthreads();
        buf = nbuf;
    }
}

extern "C" void kernel_launch(void* const* d_in, const int* in_sizes, int n_in,
                              void* d_out, int out_size) {
    const float* X0 = (const float*)d_in[0];
    const float* W  = (const float*)d_in[1];
    const float* by = (const float*)d_in[2];
    float* out = (float*)d_out;

    cudaFuncSetAttribute(antisym_rnn_kernel,
                         cudaFuncAttributeMaxDynamicSharedMemorySize, SMEM_BYTES);
    antisym_rnn_kernel<<<GRID, THREADS, SMEM_BYTES>>>(X0, W, by, out);
}